// round 4
// baseline (speedup 1.0000x reference)
#include <cuda_runtime.h>
#include <math.h>

// Problem constants (shapes fixed by the reference; E taken from in_sizes)
#define D_FEAT   128
#define HID      128
#define KDIM     256
#define TILE_M   128
#define KC       16
#define NCHUNK   (KDIM / KC)     // 16
#define THREADS  256

// ---------------- packed f32x2 helpers (sm_100+) ----------------
__device__ __forceinline__ unsigned long long pack2(float x, float y) {
    unsigned long long r;
    asm("mov.b64 %0, {%1, %2};" : "=l"(r) : "f"(x), "f"(y));
    return r;
}
__device__ __forceinline__ void fma2(unsigned long long& d,
                                     unsigned long long a,
                                     unsigned long long b) {
    asm("fma.rn.f32x2 %0, %1, %2, %0;" : "+l"(d) : "l"(a), "l"(b));
}
__device__ __forceinline__ void unpack2(unsigned long long v, float& x, float& y) {
    asm("mov.b64 {%0, %1}, %2;" : "=f"(x), "=f"(y) : "l"(v));
}

// A tile stored K-major transposed: sA[k][m], row stride padded to 132 floats
// (reduces A-transpose STS conflicts to 2-way; compute-side A reads are broadcast).
#define APAD 132

__global__ __launch_bounds__(THREADS, 2)
void edge_mlp_kernel(const float* __restrict__ zi,
                     const float* __restrict__ zj,
                     const int*   __restrict__ src,
                     const int*   __restrict__ dst,
                     const float* __restrict__ W1,   // [256,128] row-major
                     const float* __restrict__ b1,   // [128]
                     const float* __restrict__ W3,   // [128,1]
                     const float* __restrict__ b3,   // [1]
                     float*       __restrict__ out,  // [E]
                     int E)
{
    __shared__ float sA[2][KC][APAD];   // raw^T tile: sA[k][m]
    __shared__ float sB[2][KC][HID];    // W1 chunk:   sB[k][n]
    __shared__ int   sSrc[TILE_M];
    __shared__ int   sDst[TILE_M];

    const int tid = threadIdx.x;
    const int e0  = blockIdx.x * TILE_M;

    // ---- load (clamped) edge indices for this tile ----
    if (tid < TILE_M) {
        int ge = e0 + tid;
        int ce = (ge < E) ? ge : (E - 1);
        sSrc[tid] = src[ce];
        sDst[tid] = dst[ce];
    }
    __syncthreads();

    // ---- per-thread A-gather assignment: edges (le, le+64), float4 slot q ----
    const int le = tid >> 2;   // 0..63
    const int q  = tid & 3;    // which float4 of the 16-float K-chunk
    const float* bi0 = zi + (size_t)sSrc[le]      * D_FEAT + q * 4;
    const float* bj0 = zj + (size_t)sDst[le]      * D_FEAT + q * 4;
    const float* bi1 = zi + (size_t)sSrc[le + 64] * D_FEAT + q * 4;
    const float* bj1 = zj + (size_t)sDst[le + 64] * D_FEAT + q * 4;

    // ---- per-thread B-load assignment ----
    const int rB = tid >> 5;   // 0..7 (rows rB and rB+8 of the 16-row chunk)
    const int cB = tid & 31;   // float4 column

    // ---- compute-side thread mapping: 4+4 split rows/cols (conflict-free LDS) ----
    const int ty = tid >> 4;   // 0..15 -> rows {ty*4..+3, 64+ty*4..+3}
    const int tx = tid & 15;   // 0..15 -> cols {tx*4..+3, 64+tx*4..+3}

    unsigned long long acc[8][4];
#pragma unroll
    for (int i = 0; i < 8; ++i)
#pragma unroll
        for (int j = 0; j < 4; ++j) acc[i][j] = 0ull;

    float4 gA0, gA1, gB0, gB1;

    // ------- chunk load (global -> regs) -------
    auto load_chunk = [&](int c) {
        const int kc = c * KC;
        const float *p0, *p1;
        if (kc < D_FEAT) { p0 = bi0 + kc; p1 = bi1 + kc; }
        else             { p0 = bj0 + (kc - D_FEAT); p1 = bj1 + (kc - D_FEAT); }
        gA0 = *(const float4*)p0;
        gA1 = *(const float4*)p1;
        gB0 = *(const float4*)(W1 + (size_t)(kc + rB)     * HID + cB * 4);
        gB1 = *(const float4*)(W1 + (size_t)(kc + rB + 8) * HID + cB * 4);
    };
    // ------- chunk store (regs -> smem) -------
    auto store_chunk = [&](int buf) {
        float (*A)[APAD] = sA[buf];
        A[q*4+0][le]      = gA0.x; A[q*4+1][le]      = gA0.y;
        A[q*4+2][le]      = gA0.z; A[q*4+3][le]      = gA0.w;
        A[q*4+0][le+64]   = gA1.x; A[q*4+1][le+64]   = gA1.y;
        A[q*4+2][le+64]   = gA1.z; A[q*4+3][le+64]   = gA1.w;
        *(float4*)&sB[buf][rB][cB*4]     = gB0;
        *(float4*)&sB[buf][rB+8][cB*4]   = gB1;
    };
    // ------- chunk compute (smem -> acc) -------
    auto compute_chunk = [&](int buf) {
        const float (*A)[APAD] = sA[buf];
        const float (*B)[HID]  = sB[buf];
#pragma unroll
        for (int k = 0; k < KC; ++k) {
            float4 aL = *(const float4*)&A[k][ty * 4];
            float4 aH = *(const float4*)&A[k][64 + ty * 4];
            ulonglong2 bL = *(const ulonglong2*)&B[k][tx * 4];
            ulonglong2 bH = *(const ulonglong2*)&B[k][64 + tx * 4];
            const unsigned long long bv0 = bL.x, bv1 = bL.y, bv2 = bH.x, bv3 = bH.y;
            float av[8] = {aL.x, aL.y, aL.z, aL.w, aH.x, aH.y, aH.z, aH.w};
#pragma unroll
            for (int i = 0; i < 8; ++i) {
                unsigned long long ad = pack2(av[i], av[i]);
                fma2(acc[i][0], ad, bv0);
                fma2(acc[i][1], ad, bv1);
                fma2(acc[i][2], ad, bv2);
                fma2(acc[i][3], ad, bv3);
            }
        }
    };

    // ------- double-buffered mainloop -------
    load_chunk(0);
    store_chunk(0);
    __syncthreads();

#pragma unroll 1
    for (int c = 0; c < NCHUNK; ++c) {
        const int cur = c & 1;
        if (c + 1 < NCHUNK) load_chunk(c + 1);
        compute_chunk(cur);
        if (c + 1 < NCHUNK) store_chunk((c + 1) & 1);
        __syncthreads();
    }

    // ------- epilogue: bias + relu + W3 dot, shfl-reduce over tx, sigmoid -------
    const float bb3 = b3[0];
    float p[8];
#pragma unroll
    for (int i = 0; i < 8; ++i) {
        float s = 0.f;
#pragma unroll
        for (int jp = 0; jp < 4; ++jp) {
            float x0, x1;
            unpack2(acc[i][jp], x0, x1);
            const int c0 = (jp < 2) ? (tx * 4 + jp * 2)
                                    : (64 + tx * 4 + (jp - 2) * 2);
            float h0 = x0 + __ldg(&b1[c0]);     h0 = fmaxf(h0, 0.f);
            float h1 = x1 + __ldg(&b1[c0 + 1]); h1 = fmaxf(h1, 0.f);
            s = fmaf(h0, __ldg(&W3[c0]), s);
            s = fmaf(h1, __ldg(&W3[c0 + 1]), s);
        }
        p[i] = s;
    }
#pragma unroll
    for (int i = 0; i < 8; ++i) {
#pragma unroll
        for (int m = 1; m < 16; m <<= 1)
            p[i] += __shfl_xor_sync(0xffffffffu, p[i], m);
    }
    if (tx == 0) {
#pragma unroll
        for (int i = 0; i < 8; ++i) {
            const int m  = (i < 4) ? (ty * 4 + i) : (64 + ty * 4 + (i - 4));
            const int ge = e0 + m;
            if (ge < E) {
                const float lg = p[i] + bb3;
                // fast sigmoid: 1/(1+e^-x) via MUFU.EX2 path; ~1e-6 rel err,
                // 3 orders under the 1e-3 threshold.
                out[ge] = 1.0f / (1.0f + __expf(-lg));
            }
        }
    }
}

extern "C" void kernel_launch(void* const* d_in, const int* in_sizes, int n_in,
                              void* d_out, int out_size) {
    const float* zi = (const float*)d_in[0];
    const float* zj = (const float*)d_in[1];
    const int*   src = (const int*)d_in[2];
    const int*   dst = (const int*)d_in[3];
    const float* W1 = (const float*)d_in[4];
    const float* b1 = (const float*)d_in[5];
    const float* W3 = (const float*)d_in[6];
    const float* b3 = (const float*)d_in[7];
    float* out = (float*)d_out;

    const int E = in_sizes[2];
    const int grid = (E + TILE_M - 1) / TILE_M;
    edge_mlp_kernel<<<grid, THREADS>>>(zi, zj, src, dst, W1, b1, W3, b3, out, E);
}

// round 6
// speedup vs baseline: 1.8623x; 1.8623x over previous
#include <cuda_runtime.h>
#include <cuda_bf16.h>
#include <cstdint>
#include <math.h>

// ---------------- problem constants ----------------
#define DF      128
#define HID     128
#define KDIM    256
#define TILE_M  128
#define THREADS 512
#define GRID    148

// smem element strides (chosen so ldmatrix's 8 row-addresses hit 8 distinct
// 16B slots mod 128B: 144 % 128 = 16, 528 % 128 = 16)
#define AKS     72           // A row stride (elements), rows = edges, cols = k-chunk(64)
#define BKS     264          // B row stride (elements), rows = n, cols = k(256)

// ---------------- smem layout (byte offsets) ----------------
#define OFF_BHI   0                      // 128 x 264 bf16 = 67584
#define OFF_BLO   67584
#define OFF_AHI   135168                 // 128 x 72 bf16 = 18432
#define OFF_ALO   153600
#define OFF_SRC   172032
#define OFF_DST   172544
#define OFF_B1    173056
#define OFF_W3    173568
#define OFF_PART  174080                 // 128 edges x 4 warp-cols x f32 = 2048
#define SMEM_REQ  176128

__device__ __forceinline__ uint32_t smem_u32(const void* p) {
    uint32_t a;
    asm("{ .reg .u64 t; cvta.to.shared.u64 t, %1; cvt.u32.u64 %0, t; }"
        : "=r"(a) : "l"(p));
    return a;
}

// pack (f0 -> low half, f1 -> high half)
__device__ __forceinline__ uint32_t cvt2(float f0, float f1) {
    uint32_t r;
    asm("cvt.rn.bf16x2.f32 %0, %1, %2;" : "=r"(r) : "f"(f1), "f"(f0));
    return r;
}

// 8 fp32 -> 8 bf16 hi (16B) + 8 bf16 lo (16B)
__device__ __forceinline__ void cvt_store8(const float4 a, const float4 b,
                                           char* hp_ptr, char* lp_ptr) {
    float f[8] = {a.x, a.y, a.z, a.w, b.x, b.y, b.z, b.w};
    uint32_t hp[4], lp[4];
#pragma unroll
    for (int p = 0; p < 4; ++p) {
        float f0 = f[2*p], f1 = f[2*p+1];
        uint32_t h = cvt2(f0, f1);
        hp[p] = h;
        float g0 = __uint_as_float(h << 16);
        float g1 = __uint_as_float(h & 0xFFFF0000u);
        lp[p] = cvt2(f0 - g0, f1 - g1);
    }
    *(uint4*)hp_ptr = make_uint4(hp[0], hp[1], hp[2], hp[3]);
    *(uint4*)lp_ptr = make_uint4(lp[0], lp[1], lp[2], lp[3]);
}

#define LDSM_X4(r0, r1, r2, r3, addr) \
    asm volatile("ldmatrix.sync.aligned.m8n8.x4.shared.b16 {%0,%1,%2,%3}, [%4];" \
                 : "=r"(r0), "=r"(r1), "=r"(r2), "=r"(r3) : "r"(addr))

#define MMA16816(d, a0, a1, a2, a3, b0, b1) \
    asm volatile("mma.sync.aligned.m16n8k16.row.col.f32.bf16.bf16.f32 " \
                 "{%0,%1,%2,%3}, {%4,%5,%6,%7}, {%8,%9}, {%0,%1,%2,%3};" \
                 : "+f"((d)[0]), "+f"((d)[1]), "+f"((d)[2]), "+f"((d)[3]) \
                 : "r"(a0), "r"(a1), "r"(a2), "r"(a3), "r"(b0), "r"(b1))

__global__ __launch_bounds__(THREADS, 1)
void edge_mlp_hmma(const float* __restrict__ zi, const float* __restrict__ zj,
                   const int* __restrict__ src, const int* __restrict__ dst,
                   const float* __restrict__ W1, const float* __restrict__ b1,
                   const float* __restrict__ W3, const float* __restrict__ b3,
                   float* __restrict__ out, int E, int ntiles)
{
    extern __shared__ char sm[];
    const uint32_t smu = smem_u32(sm);

    const int tid  = threadIdx.x;
    const int wid  = tid >> 5;
    const int lane = tid & 31;

    // ---- one-time: W1[k][n] -> B[n][k] hi/lo bf16 (resident) ----
    for (int it = tid; it < KDIM * HID; it += THREADS) {
        int k = it >> 7, n = it & 127;
        float x = W1[it];
        __nv_bfloat16 hb = __float2bfloat16(x);
        float l = x - __bfloat162float(hb);
        __nv_bfloat16 lb = __float2bfloat16(l);
        uint32_t off = (uint32_t)(n * BKS + k) * 2u;
        *(__nv_bfloat16*)(sm + OFF_BHI + off) = hb;
        *(__nv_bfloat16*)(sm + OFF_BLO + off) = lb;
    }
    if (tid < HID) {
        ((float*)(sm + OFF_B1))[tid] = b1[tid];
        ((float*)(sm + OFF_W3))[tid] = W3[tid];
    }
    __syncthreads();

    const float bb3 = __ldg(b3);
    int* sSrc = (int*)(sm + OFF_SRC);
    int* sDst = (int*)(sm + OFF_DST);
    const float* sb1 = (const float*)(sm + OFF_B1);
    const float* sw3 = (const float*)(sm + OFF_W3);
    float* spart = (float*)(sm + OFF_PART);

    // ---- warp tiling: 4x4 warps, each 32(M) x 32(N) ----
    const int warp_m = wid >> 2;          // 0..3
    const int warp_n = wid & 3;           // 0..3
    const int m0 = warp_m * 32;
    const int n0 = warp_n * 32;

    // ldmatrix per-lane base addresses
    // A (rows = m, cols = k within 64-chunk): lanes 0-15 khalf0, 16-31 khalf1
    const int rowA   = lane & 15;
    const int khalfA = lane >> 4;
    uint32_t abase[2][2];                 // [mt][term]
#pragma unroll
    for (int mt = 0; mt < 2; ++mt) {
        uint32_t rb = (uint32_t)((m0 + mt * 16 + rowA) * AKS + khalfA * 8) * 2u;
        abase[mt][0] = smu + OFF_AHI + rb;
        abase[mt][1] = smu + OFF_ALO + rb;
    }
    // B (rows = n, cols = k global): lanes {0-7,8-15,16-23,24-31} ->
    // (n0-7,k0-7),(n0-7,k8-15),(n8-15,k0-7),(n8-15,k8-15)
    const int rowB   = (lane & 7) + ((lane >= 16) ? 8 : 0);
    const int khalfB = (lane >> 3) & 1;
    uint32_t bbase[2][2];                 // [nt][term]
#pragma unroll
    for (int nt = 0; nt < 2; ++nt) {
        uint32_t rb = (uint32_t)((n0 + nt * 16 + rowB) * BKS + khalfB * 8) * 2u;
        bbase[nt][0] = smu + OFF_BHI + rb;
        bbase[nt][1] = smu + OFF_BLO + rb;
    }

    // gather assignment: edge e, 16-float slice qq within 64-float chunk
    const int e  = tid >> 2;
    const int qq = tid & 3;
    const uint32_t a_sts = (uint32_t)(e * AKS + qq * 16) * 2u;   // byte off in A buf

    for (int tile = blockIdx.x; tile < ntiles; tile += GRID) {
        const int e0 = tile * TILE_M;
        if (tid < TILE_M) {
            int ge = e0 + tid; sSrc[tid] = src[ge < E ? ge : (E - 1)];
        } else if (tid < 2 * TILE_M) {
            int j = tid - TILE_M; int ge = e0 + j; sDst[j] = dst[ge < E ? ge : (E - 1)];
        }
        __syncthreads();

        const float* pi = zi + (size_t)sSrc[e] * DF + qq * 16;
        const float* pj = zj + (size_t)sDst[e] * DF + qq * 16;

        float acc[2][4][4];
#pragma unroll
        for (int mt = 0; mt < 2; ++mt)
#pragma unroll
            for (int nt8 = 0; nt8 < 4; ++nt8)
#pragma unroll
                for (int r = 0; r < 4; ++r) acc[mt][nt8][r] = 0.f;

        float4 r0 = *(const float4*)(pi + 0);
        float4 r1 = *(const float4*)(pi + 4);
        float4 r2 = *(const float4*)(pi + 8);
        float4 r3 = *(const float4*)(pi + 12);

#pragma unroll 1
        for (int c = 0; c < 4; ++c) {
            // ---- store chunk c (prior mma finished: barrier below) ----
            cvt_store8(r0, r1, sm + OFF_AHI + a_sts,      sm + OFF_ALO + a_sts);
            cvt_store8(r2, r3, sm + OFF_AHI + a_sts + 16, sm + OFF_ALO + a_sts + 16);
            if (c < 3) {   // prefetch next chunk while mma runs
                const float* np = (c == 0) ? (pi + 64) : ((c == 1) ? pj : (pj + 64));
                r0 = *(const float4*)(np + 0);
                r1 = *(const float4*)(np + 4);
                r2 = *(const float4*)(np + 8);
                r3 = *(const float4*)(np + 12);
            }
            __syncthreads();

            const uint32_t bko = (uint32_t)c * 128u;   // chunk k-offset in bytes
#pragma unroll
            for (int ks = 0; ks < 4; ++ks) {
                const uint32_t ao = (uint32_t)ks * 32u;
                const uint32_t bo = bko + (uint32_t)ks * 32u;
                uint32_t Ah[2][4], Al[2][4], Bh[2][4], Bl[2][4];
#pragma unroll
                for (int mt = 0; mt < 2; ++mt) {
                    LDSM_X4(Ah[mt][0], Ah[mt][1], Ah[mt][2], Ah[mt][3], abase[mt][0] + ao);
                    LDSM_X4(Al[mt][0], Al[mt][1], Al[mt][2], Al[mt][3], abase[mt][1] + ao);
                }
#pragma unroll
                for (int nt = 0; nt < 2; ++nt) {
                    LDSM_X4(Bh[nt][0], Bh[nt][1], Bh[nt][2], Bh[nt][3], bbase[nt][0] + bo);
                    LDSM_X4(Bl[nt][0], Bl[nt][1], Bl[nt][2], Bl[nt][3], bbase[nt][1] + bo);
                }
#pragma unroll
                for (int mt = 0; mt < 2; ++mt) {
#pragma unroll
                    for (int nt8 = 0; nt8 < 4; ++nt8) {
                        const int nt = nt8 >> 1, hf = (nt8 & 1) * 2;
                        MMA16816(acc[mt][nt8], Ah[mt][0], Ah[mt][1], Ah[mt][2], Ah[mt][3],
                                 Bh[nt][hf], Bh[nt][hf + 1]);
                        MMA16816(acc[mt][nt8], Al[mt][0], Al[mt][1], Al[mt][2], Al[mt][3],
                                 Bh[nt][hf], Bh[nt][hf + 1]);
                        MMA16816(acc[mt][nt8], Ah[mt][0], Ah[mt][1], Ah[mt][2], Ah[mt][3],
                                 Bl[nt][hf], Bl[nt][hf + 1]);
                    }
                }
            }
            __syncthreads();
        }

        // ---- epilogue: bias+relu+W3 from register fragments ----
        const int g  = lane >> 2;          // fragment row group
        const int c0 = (lane & 3) * 2;     // fragment col pair
        float p[4];                         // [mt*2 + rr]: rows m0+mt*16+rr*8+g
#pragma unroll
        for (int mt = 0; mt < 2; ++mt) {
            float s0 = 0.f, s1 = 0.f;
#pragma unroll
            for (int nt8 = 0; nt8 < 4; ++nt8) {
                const int n = n0 + nt8 * 8 + c0;
                const float w0 = sw3[n], w1 = sw3[n + 1];
                const float bb0 = sb1[n], bb1 = sb1[n + 1];
                s0 = fmaf(fmaxf(acc[mt][nt8][0] + bb0, 0.f), w0, s0);
                s0 = fmaf(fmaxf(acc[mt][nt8][1] + bb1, 0.f), w1, s0);
                s1 = fmaf(fmaxf(acc[mt][nt8][2] + bb0, 0.f), w0, s1);
                s1 = fmaf(fmaxf(acc[mt][nt8][3] + bb1, 0.f), w1, s1);
            }
            p[mt * 2 + 0] = s0;
            p[mt * 2 + 1] = s1;
        }
#pragma unroll
        for (int i = 0; i < 4; ++i) {
            p[i] += __shfl_xor_sync(0xffffffffu, p[i], 1);
            p[i] += __shfl_xor_sync(0xffffffffu, p[i], 2);
        }
        if ((lane & 3) == 0) {
#pragma unroll
            for (int i = 0; i < 4; ++i) {
                const int m = m0 + (i >> 1) * 16 + (i & 1) * 8 + g;
                spart[m * 4 + warp_n] = p[i];
            }
        }
        __syncthreads();
        if (tid < TILE_M) {
            const int ge = e0 + tid;
            if (ge < E) {
                float tot = spart[tid * 4 + 0] + spart[tid * 4 + 1]
                          + spart[tid * 4 + 2] + spart[tid * 4 + 3] + bb3;
                out[ge] = 1.0f / (1.0f + __expf(-tot));
            }
        }
        __syncthreads();
    }
}

extern "C" void kernel_launch(void* const* d_in, const int* in_sizes, int n_in,
                              void* d_out, int out_size) {
    const float* zi = (const float*)d_in[0];
    const float* zj = (const float*)d_in[1];
    const int*   src = (const int*)d_in[2];
    const int*   dst = (const int*)d_in[3];
    const float* W1 = (const float*)d_in[4];
    const float* b1 = (const float*)d_in[5];
    const float* W3 = (const float*)d_in[6];
    const float* b3 = (const float*)d_in[7];
    float* out = (float*)d_out;

    const int E = in_sizes[2];
    const int ntiles = (E + TILE_M - 1) / TILE_M;

    cudaFuncSetAttribute(edge_mlp_hmma,
                         cudaFuncAttributeMaxDynamicSharedMemorySize, SMEM_REQ);
    edge_mlp_hmma<<<GRID, THREADS, SMEM_REQ>>>(zi, zj, src, dst, W1, b1, W3, b3,
                                               out, E, ntiles);
}

// round 7
// speedup vs baseline: 2.0829x; 1.1185x over previous
#include <cuda_runtime.h>
#include <cuda_bf16.h>
#include <cstdint>
#include <math.h>

// ---------------- problem constants ----------------
#define DF      128
#define HID     128
#define KDIM    256
#define TILE_M  128
#define THREADS 512
#define GRID    148

// smem element strides: ldmatrix row addresses hit 8 distinct 16B slots mod 128B
// (144 % 128 = 16, 528 % 128 = 16)
#define AKS     72           // A row stride (elements); rows = edges, cols = 64-k chunk
#define BKS     264          // B row stride (elements); rows = n, cols = k(256)

#define A_TERM_BYTES  18432              // 128 * 72 * 2
#define A_BUF_BYTES   36864              // hi + lo

// ---------------- smem layout (byte offsets) ----------------
#define OFF_BHI   0                      // 128 x 264 bf16 = 67584
#define OFF_BLO   67584
#define OFF_A     135168                 // [buf2][term2] x 18432 = 73728
#define OFF_B1    208896
#define OFF_W3    209408
#define OFF_PART  209920                 // 128 x 4 x f32
#define SMEM_REQ  211968

__device__ __forceinline__ uint32_t smem_u32(const void* p) {
    uint32_t a;
    asm("{ .reg .u64 t; cvta.to.shared.u64 t, %1; cvt.u32.u64 %0, t; }"
        : "=r"(a) : "l"(p));
    return a;
}

// pack (f0 -> low half, f1 -> high half)
__device__ __forceinline__ uint32_t cvt2(float f0, float f1) {
    uint32_t r;
    asm("cvt.rn.bf16x2.f32 %0, %1, %2;" : "=r"(r) : "f"(f1), "f"(f0));
    return r;
}

// 8 fp32 -> 8 bf16 hi (16B) + 8 bf16 lo (16B)
__device__ __forceinline__ void cvt_store8(const float4 a, const float4 b,
                                           char* hp_ptr, char* lp_ptr) {
    float f[8] = {a.x, a.y, a.z, a.w, b.x, b.y, b.z, b.w};
    uint32_t hp[4], lp[4];
#pragma unroll
    for (int p = 0; p < 4; ++p) {
        float f0 = f[2*p], f1 = f[2*p+1];
        uint32_t h = cvt2(f0, f1);
        hp[p] = h;
        float g0 = __uint_as_float(h << 16);
        float g1 = __uint_as_float(h & 0xFFFF0000u);
        lp[p] = cvt2(f0 - g0, f1 - g1);
    }
    *(uint4*)hp_ptr = make_uint4(hp[0], hp[1], hp[2], hp[3]);
    *(uint4*)lp_ptr = make_uint4(lp[0], lp[1], lp[2], lp[3]);
}

#define LDSM_X4(r0, r1, r2, r3, addr) \
    asm volatile("ldmatrix.sync.aligned.m8n8.x4.shared.b16 {%0,%1,%2,%3}, [%4];" \
                 : "=r"(r0), "=r"(r1), "=r"(r2), "=r"(r3) : "r"(addr))

#define MMA16816(d, a0, a1, a2, a3, b0, b1) \
    asm volatile("mma.sync.aligned.m16n8k16.row.col.f32.bf16.bf16.f32 " \
                 "{%0,%1,%2,%3}, {%4,%5,%6,%7}, {%8,%9}, {%0,%1,%2,%3};" \
                 : "+f"((d)[0]), "+f"((d)[1]), "+f"((d)[2]), "+f"((d)[3]) \
                 : "r"(a0), "r"(a1), "r"(a2), "r"(a3), "r"(b0), "r"(b1))

__global__ __launch_bounds__(THREADS, 1)
void edge_mlp_hmma(const float* __restrict__ zi, const float* __restrict__ zj,
                   const int* __restrict__ src, const int* __restrict__ dst,
                   const float* __restrict__ W1, const float* __restrict__ b1,
                   const float* __restrict__ W3, const float* __restrict__ b3,
                   float* __restrict__ out, int E, int ntiles)
{
    extern __shared__ char sm[];
    const uint32_t smu = smem_u32(sm);

    const int tid  = threadIdx.x;
    const int wid  = tid >> 5;
    const int lane = tid & 31;

    // ---- one-time: W1[k][n] -> B[n][k] hi/lo bf16 (resident) ----
    for (int it = tid; it < KDIM * HID; it += THREADS) {
        int k = it >> 7, n = it & 127;
        float x = W1[it];
        __nv_bfloat16 hb = __float2bfloat16(x);
        float l = x - __bfloat162float(hb);
        __nv_bfloat16 lb = __float2bfloat16(l);
        uint32_t off = (uint32_t)(n * BKS + k) * 2u;
        *(__nv_bfloat16*)(sm + OFF_BHI + off) = hb;
        *(__nv_bfloat16*)(sm + OFF_BLO + off) = lb;
    }
    if (tid < HID) {
        ((float*)(sm + OFF_B1))[tid] = b1[tid];
        ((float*)(sm + OFF_W3))[tid] = W3[tid];
    }
    __syncthreads();

    const float bb3 = __ldg(b3);
    const float* sb1 = (const float*)(sm + OFF_B1);
    const float* sw3 = (const float*)(sm + OFF_W3);
    float* spart = (float*)(sm + OFF_PART);

    // ---- warp tiling: 4x4 warps, each 32(M) x 32(N) ----
    const int warp_m = wid >> 2;
    const int warp_n = wid & 3;
    const int m0 = warp_m * 32;
    const int n0 = warp_n * 32;

    // ldmatrix per-lane base addresses (term 0 = hi; +A_TERM_BYTES = lo)
    const int rowA   = lane & 15;
    const int khalfA = lane >> 4;
    uint32_t abase[2];                   // [mt], hi-term, buf0
#pragma unroll
    for (int mt = 0; mt < 2; ++mt)
        abase[mt] = smu + OFF_A
                  + (uint32_t)((m0 + mt * 16 + rowA) * AKS + khalfA * 8) * 2u;

    const int rowB   = (lane & 7) + ((lane >= 16) ? 8 : 0);
    const int khalfB = (lane >> 3) & 1;
    uint32_t bbase[2];                   // [nt], hi-term
#pragma unroll
    for (int nt = 0; nt < 2; ++nt)
        bbase[nt] = smu + OFF_BHI
                  + (uint32_t)((n0 + nt * 16 + rowB) * BKS + khalfB * 8) * 2u;

    // gather assignment: edge slot e, 16-float slice qq of the 64-float chunk
    const int e  = tid >> 2;
    const int qq = tid & 3;
    const uint32_t a_sts = (uint32_t)(e * AKS + qq * 16) * 2u;

    // ---- prologue: first tile's indices + chunk0 prefetch ----
    int ge0 = blockIdx.x * TILE_M + e;
    int isrc = __ldg(&src[ge0 < E ? ge0 : (E - 1)]);
    int idst = __ldg(&dst[ge0 < E ? ge0 : (E - 1)]);
    const float* pre = zi + (size_t)isrc * DF + qq * 16;
    float4 r0 = *(const float4*)(pre + 0);
    float4 r1 = *(const float4*)(pre + 4);
    float4 r2 = *(const float4*)(pre + 8);
    float4 r3 = *(const float4*)(pre + 12);

    int nsrc = 0, ndst = 0;

    for (int tile = blockIdx.x; tile < ntiles; tile += GRID) {
        const int e0 = tile * TILE_M;
        const float* pi = zi + (size_t)isrc * DF + qq * 16;
        const float* pj = zj + (size_t)idst * DF + qq * 16;

        float acc[2][4][4];
#pragma unroll
        for (int mt = 0; mt < 2; ++mt)
#pragma unroll
            for (int nt8 = 0; nt8 < 4; ++nt8)
#pragma unroll
                for (int r = 0; r < 4; ++r) acc[mt][nt8][r] = 0.f;

#pragma unroll 1
        for (int c = 0; c < 4; ++c) {
            const uint32_t bufo = (uint32_t)(c & 1) * A_BUF_BYTES;
            // store chunk c into buffer (buf b last read at chunk c-2; that
            // read completed before the sync of chunk c-1)
            char* ah = sm + OFF_A + bufo;
            char* al = ah + A_TERM_BYTES;
            cvt_store8(r0, r1, ah + a_sts,      al + a_sts);
            cvt_store8(r2, r3, ah + a_sts + 16, al + a_sts + 16);

            // issue next LDGs (hidden under this chunk's mma)
            if (c == 0) {
                r0 = *(const float4*)(pi + 64); r1 = *(const float4*)(pi + 68);
                r2 = *(const float4*)(pi + 72); r3 = *(const float4*)(pi + 76);
            } else if (c == 1) {
                r0 = *(const float4*)(pj + 0);  r1 = *(const float4*)(pj + 4);
                r2 = *(const float4*)(pj + 8);  r3 = *(const float4*)(pj + 12);
            } else if (c == 2) {
                r0 = *(const float4*)(pj + 64); r1 = *(const float4*)(pj + 68);
                r2 = *(const float4*)(pj + 72); r3 = *(const float4*)(pj + 76);
                int nge = (tile + GRID < ntiles) ? (tile + GRID) * TILE_M + e : 0;
                nge = nge < E ? nge : (E - 1);
                nsrc = __ldg(&src[nge]);
                ndst = __ldg(&dst[nge]);
            } else {
                const float* np = zi + (size_t)nsrc * DF + qq * 16;
                r0 = *(const float4*)(np + 0);  r1 = *(const float4*)(np + 4);
                r2 = *(const float4*)(np + 8);  r3 = *(const float4*)(np + 12);
            }

            __syncthreads();   // single barrier per chunk

            const uint32_t bko = (uint32_t)c * 128u;
#pragma unroll
            for (int ks = 0; ks < 4; ++ks) {
                const uint32_t ao = bufo + (uint32_t)ks * 32u;
                const uint32_t bo = bko + (uint32_t)ks * 32u;
                uint32_t Ah[2][4], Al[2][4], Bh[2][4], Bl[2][4];
#pragma unroll
                for (int mt = 0; mt < 2; ++mt) {
                    LDSM_X4(Ah[mt][0], Ah[mt][1], Ah[mt][2], Ah[mt][3],
                            abase[mt] + ao);
                    LDSM_X4(Al[mt][0], Al[mt][1], Al[mt][2], Al[mt][3],
                            abase[mt] + ao + A_TERM_BYTES);
                }
#pragma unroll
                for (int nt = 0; nt < 2; ++nt) {
                    LDSM_X4(Bh[nt][0], Bh[nt][1], Bh[nt][2], Bh[nt][3],
                            bbase[nt] + bo);
                    LDSM_X4(Bl[nt][0], Bl[nt][1], Bl[nt][2], Bl[nt][3],
                            bbase[nt] + bo + 67584u);
                }
                // term-ordered: same-accumulator MMAs are 8 issues apart
#pragma unroll
                for (int mt = 0; mt < 2; ++mt)
#pragma unroll
                    for (int nt8 = 0; nt8 < 4; ++nt8) {
                        const int nt = nt8 >> 1, hf = (nt8 & 1) * 2;
                        MMA16816(acc[mt][nt8],
                                 Ah[mt][0], Ah[mt][1], Ah[mt][2], Ah[mt][3],
                                 Bh[nt][hf], Bh[nt][hf + 1]);
                    }
#pragma unroll
                for (int mt = 0; mt < 2; ++mt)
#pragma unroll
                    for (int nt8 = 0; nt8 < 4; ++nt8) {
                        const int nt = nt8 >> 1, hf = (nt8 & 1) * 2;
                        MMA16816(acc[mt][nt8],
                                 Al[mt][0], Al[mt][1], Al[mt][2], Al[mt][3],
                                 Bh[nt][hf], Bh[nt][hf + 1]);
                    }
#pragma unroll
                for (int mt = 0; mt < 2; ++mt)
#pragma unroll
                    for (int nt8 = 0; nt8 < 4; ++nt8) {
                        const int nt = nt8 >> 1, hf = (nt8 & 1) * 2;
                        MMA16816(acc[mt][nt8],
                                 Ah[mt][0], Ah[mt][1], Ah[mt][2], Ah[mt][3],
                                 Bl[nt][hf], Bl[nt][hf + 1]);
                    }
            }
        }

        // ---- epilogue: bias+relu+W3 from register fragments ----
        const int g  = lane >> 2;
        const int c0 = (lane & 3) * 2;
        float p[4];
#pragma unroll
        for (int mt = 0; mt < 2; ++mt) {
            float s0 = 0.f, s1 = 0.f;
#pragma unroll
            for (int nt8 = 0; nt8 < 4; ++nt8) {
                const int n = n0 + nt8 * 8 + c0;
                const float w0 = sw3[n], w1 = sw3[n + 1];
                const float bb0 = sb1[n], bb1 = sb1[n + 1];
                s0 = fmaf(fmaxf(acc[mt][nt8][0] + bb0, 0.f), w0, s0);
                s0 = fmaf(fmaxf(acc[mt][nt8][1] + bb1, 0.f), w1, s0);
                s1 = fmaf(fmaxf(acc[mt][nt8][2] + bb0, 0.f), w0, s1);
                s1 = fmaf(fmaxf(acc[mt][nt8][3] + bb1, 0.f), w1, s1);
            }
            p[mt * 2 + 0] = s0;
            p[mt * 2 + 1] = s1;
        }
#pragma unroll
        for (int i = 0; i < 4; ++i) {
            p[i] += __shfl_xor_sync(0xffffffffu, p[i], 1);
            p[i] += __shfl_xor_sync(0xffffffffu, p[i], 2);
        }
        if ((lane & 3) == 0) {
#pragma unroll
            for (int i = 0; i < 4; ++i) {
                const int m = m0 + (i >> 1) * 16 + (i & 1) * 8 + g;
                spart[m * 4 + warp_n] = p[i];
            }
        }
        isrc = nsrc;          // roll prefetched indices into place
        idst = ndst;
        __syncthreads();
        if (tid < TILE_M) {
            const int ge = e0 + tid;
            if (ge < E) {
                float tot = spart[tid * 4 + 0] + spart[tid * 4 + 1]
                          + spart[tid * 4 + 2] + spart[tid * 4 + 3] + bb3;
                out[ge] = 1.0f / (1.0f + __expf(-tot));
            }
        }
        __syncthreads();
    }
}

extern "C" void kernel_launch(void* const* d_in, const int* in_sizes, int n_in,
                              void* d_out, int out_size) {
    const float* zi = (const float*)d_in[0];
    const float* zj = (const float*)d_in[1];
    const int*   src = (const int*)d_in[2];
    const int*   dst = (const int*)d_in[3];
    const float* W1 = (const float*)d_in[4];
    const float* b1 = (const float*)d_in[5];
    const float* W3 = (const float*)d_in[6];
    const float* b3 = (const float*)d_in[7];
    float* out = (float*)d_out;

    const int E = in_sizes[2];
    const int ntiles = (E + TILE_M - 1) / TILE_M;

    cudaFuncSetAttribute(edge_mlp_hmma,
                         cudaFuncAttributeMaxDynamicSharedMemorySize, SMEM_REQ);
    edge_mlp_hmma<<<GRID, THREADS, SMEM_REQ>>>(zi, zj, src, dst, W1, b1, W3, b3,
                                               out, E, ntiles);
}

// round 8
// speedup vs baseline: 2.0859x; 1.0015x over previous
#include <cuda_runtime.h>
#include <cuda_bf16.h>
#include <cstdint>
#include <math.h>

// ---------------- problem constants ----------------
#define DF      128
#define HID     128
#define KDIM    256
#define TILE_M  128
#define THREADS 512
#define GRID    148

// smem element strides: ldmatrix row addresses hit 8 distinct 16B slots mod 128B
// (144 % 128 = 16, 528 % 128 = 16)
#define AKS     72           // A row stride (elements); rows = edges, cols = 64-k chunk
#define BKS     264          // B row stride (elements); rows = n, cols = k(256)

#define A_TERM_BYTES  18432              // 128 * 72 * 2
#define A_BUF_BYTES   36864              // hi + lo

// ---------------- smem layout (byte offsets) ----------------
#define OFF_BHI   0                      // 128 x 264 bf16 = 67584
#define OFF_BLO   67584
#define OFF_A     135168                 // [buf2][term2] x 18432 = 73728
#define OFF_B1    208896
#define OFF_W3    209408
#define OFF_PART  209920                 // 128 x 4 x f32
#define SMEM_REQ  211968

__device__ __forceinline__ uint32_t smem_u32(const void* p) {
    uint32_t a;
    asm("{ .reg .u64 t; cvta.to.shared.u64 t, %1; cvt.u32.u64 %0, t; }"
        : "=r"(a) : "l"(p));
    return a;
}

// pack (f0 -> low half, f1 -> high half)
__device__ __forceinline__ uint32_t cvt2(float f0, float f1) {
    uint32_t r;
    asm("cvt.rn.bf16x2.f32 %0, %1, %2;" : "=r"(r) : "f"(f1), "f"(f0));
    return r;
}

// 8 fp32 -> 8 bf16 hi (16B) + 8 bf16 lo (16B)
__device__ __forceinline__ void cvt_store8(const float4 a, const float4 b,
                                           char* hp_ptr, char* lp_ptr) {
    float f[8] = {a.x, a.y, a.z, a.w, b.x, b.y, b.z, b.w};
    uint32_t hp[4], lp[4];
#pragma unroll
    for (int p = 0; p < 4; ++p) {
        float f0 = f[2*p], f1 = f[2*p+1];
        uint32_t h = cvt2(f0, f1);
        hp[p] = h;
        float g0 = __uint_as_float(h << 16);
        float g1 = __uint_as_float(h & 0xFFFF0000u);
        lp[p] = cvt2(f0 - g0, f1 - g1);
    }
    *(uint4*)hp_ptr = make_uint4(hp[0], hp[1], hp[2], hp[3]);
    *(uint4*)lp_ptr = make_uint4(lp[0], lp[1], lp[2], lp[3]);
}

#define LDSM_X4(r0, r1, r2, r3, addr) \
    asm volatile("ldmatrix.sync.aligned.m8n8.x4.shared.b16 {%0,%1,%2,%3}, [%4];" \
                 : "=r"(r0), "=r"(r1), "=r"(r2), "=r"(r3) : "r"(addr))

#define MMA16816(d, a0, a1, a2, a3, b0, b1) \
    asm volatile("mma.sync.aligned.m16n8k16.row.col.f32.bf16.bf16.f32 " \
                 "{%0,%1,%2,%3}, {%4,%5,%6,%7}, {%8,%9}, {%0,%1,%2,%3};" \
                 : "+f"((d)[0]), "+f"((d)[1]), "+f"((d)[2]), "+f"((d)[3]) \
                 : "r"(a0), "r"(a1), "r"(a2), "r"(a3), "r"(b0), "r"(b1))

__global__ __launch_bounds__(THREADS, 1)
void edge_mlp_hmma(const float* __restrict__ zi, const float* __restrict__ zj,
                   const int* __restrict__ src, const int* __restrict__ dst,
                   const float* __restrict__ W1, const float* __restrict__ b1,
                   const float* __restrict__ W3, const float* __restrict__ b3,
                   float* __restrict__ out, int E, int ntiles)
{
    extern __shared__ char sm[];
    const uint32_t smu = smem_u32(sm);

    const int tid  = threadIdx.x;
    const int wid  = tid >> 5;
    const int lane = tid & 31;

    // ---- one-time: W1[k][n] -> B[n][k] hi/lo bf16 (resident) ----
    for (int it = tid; it < KDIM * HID; it += THREADS) {
        int k = it >> 7, n = it & 127;
        float x = W1[it];
        __nv_bfloat16 hb = __float2bfloat16(x);
        float l = x - __bfloat162float(hb);
        __nv_bfloat16 lb = __float2bfloat16(l);
        uint32_t off = (uint32_t)(n * BKS + k) * 2u;
        *(__nv_bfloat16*)(sm + OFF_BHI + off) = hb;
        *(__nv_bfloat16*)(sm + OFF_BLO + off) = lb;
    }
    if (tid < HID) {
        ((float*)(sm + OFF_B1))[tid] = b1[tid];
        ((float*)(sm + OFF_W3))[tid] = W3[tid];
    }
    __syncthreads();

    const float bb3 = __ldg(b3);
    const float* sb1 = (const float*)(sm + OFF_B1);
    const float* sw3 = (const float*)(sm + OFF_W3);
    float* spart = (float*)(sm + OFF_PART);

    // ---- warp tiling: 4x4 warps, each 32(M) x 32(N) ----
    const int warp_m = wid >> 2;
    const int warp_n = wid & 3;
    const int m0 = warp_m * 32;
    const int n0 = warp_n * 32;

    // ldmatrix per-lane base addresses (term 0 = hi; +A_TERM_BYTES = lo)
    const int rowA   = lane & 15;
    const int khalfA = lane >> 4;
    uint32_t abase[2];                   // [mt], hi-term, buf0
#pragma unroll
    for (int mt = 0; mt < 2; ++mt)
        abase[mt] = smu + OFF_A
                  + (uint32_t)((m0 + mt * 16 + rowA) * AKS + khalfA * 8) * 2u;

    const int rowB   = (lane & 7) + ((lane >= 16) ? 8 : 0);
    const int khalfB = (lane >> 3) & 1;
    uint32_t bbase[2];                   // [nt], hi-term
#pragma unroll
    for (int nt = 0; nt < 2; ++nt)
        bbase[nt] = smu + OFF_BHI
                  + (uint32_t)((n0 + nt * 16 + rowB) * BKS + khalfB * 8) * 2u;

    // gather assignment: edge slot e, 16-float slice qq of the 64-float chunk
    const int e  = tid >> 2;
    const int qq = tid & 3;
    const uint32_t a_sts = (uint32_t)(e * AKS + qq * 16) * 2u;

    // ---- prologue: first tile's indices + chunk0 prefetch ----
    int ge0 = blockIdx.x * TILE_M + e;
    int isrc = __ldg(&src[ge0 < E ? ge0 : (E - 1)]);
    int idst = __ldg(&dst[ge0 < E ? ge0 : (E - 1)]);
    const float* pre = zi + (size_t)isrc * DF + qq * 16;
    float4 r0 = *(const float4*)(pre + 0);
    float4 r1 = *(const float4*)(pre + 4);
    float4 r2 = *(const float4*)(pre + 8);
    float4 r3 = *(const float4*)(pre + 12);

    int nsrc = 0, ndst = 0;

    for (int tile = blockIdx.x; tile < ntiles; tile += GRID) {
        const int e0 = tile * TILE_M;
        const float* pi = zi + (size_t)isrc * DF + qq * 16;
        const float* pj = zj + (size_t)idst * DF + qq * 16;

        float acc[2][4][4];
#pragma unroll
        for (int mt = 0; mt < 2; ++mt)
#pragma unroll
            for (int nt8 = 0; nt8 < 4; ++nt8)
#pragma unroll
                for (int r = 0; r < 4; ++r) acc[mt][nt8][r] = 0.f;

#pragma unroll 1
        for (int c = 0; c < 4; ++c) {
            const uint32_t bufo = (uint32_t)(c & 1) * A_BUF_BYTES;
            // store chunk c into buffer (buf b last read at chunk c-2; that
            // read completed before the sync of chunk c-1)
            char* ah = sm + OFF_A + bufo;
            char* al = ah + A_TERM_BYTES;
            cvt_store8(r0, r1, ah + a_sts,      al + a_sts);
            cvt_store8(r2, r3, ah + a_sts + 16, al + a_sts + 16);

            // issue next LDGs (hidden under this chunk's mma)
            if (c == 0) {
                r0 = *(const float4*)(pi + 64); r1 = *(const float4*)(pi + 68);
                r2 = *(const float4*)(pi + 72); r3 = *(const float4*)(pi + 76);
            } else if (c == 1) {
                r0 = *(const float4*)(pj + 0);  r1 = *(const float4*)(pj + 4);
                r2 = *(const float4*)(pj + 8);  r3 = *(const float4*)(pj + 12);
            } else if (c == 2) {
                r0 = *(const float4*)(pj + 64); r1 = *(const float4*)(pj + 68);
                r2 = *(const float4*)(pj + 72); r3 = *(const float4*)(pj + 76);
                int nge = (tile + GRID < ntiles) ? (tile + GRID) * TILE_M + e : 0;
                nge = nge < E ? nge : (E - 1);
                nsrc = __ldg(&src[nge]);
                ndst = __ldg(&dst[nge]);
            } else {
                const float* np = zi + (size_t)nsrc * DF + qq * 16;
                r0 = *(const float4*)(np + 0);  r1 = *(const float4*)(np + 4);
                r2 = *(const float4*)(np + 8);  r3 = *(const float4*)(np + 12);
            }

            __syncthreads();   // single barrier per chunk

            const uint32_t bko = (uint32_t)c * 128u;
#pragma unroll
            for (int ks = 0; ks < 4; ++ks) {
                const uint32_t ao = bufo + (uint32_t)ks * 32u;
                const uint32_t bo = bko + (uint32_t)ks * 32u;
                uint32_t Ah[2][4], Al[2][4], Bh[2][4], Bl[2][4];
#pragma unroll
                for (int mt = 0; mt < 2; ++mt) {
                    LDSM_X4(Ah[mt][0], Ah[mt][1], Ah[mt][2], Ah[mt][3],
                            abase[mt] + ao);
                    LDSM_X4(Al[mt][0], Al[mt][1], Al[mt][2], Al[mt][3],
                            abase[mt] + ao + A_TERM_BYTES);
                }
#pragma unroll
                for (int nt = 0; nt < 2; ++nt) {
                    LDSM_X4(Bh[nt][0], Bh[nt][1], Bh[nt][2], Bh[nt][3],
                            bbase[nt] + bo);
                    LDSM_X4(Bl[nt][0], Bl[nt][1], Bl[nt][2], Bl[nt][3],
                            bbase[nt] + bo + 67584u);
                }
                // term-ordered: same-accumulator MMAs are 8 issues apart
#pragma unroll
                for (int mt = 0; mt < 2; ++mt)
#pragma unroll
                    for (int nt8 = 0; nt8 < 4; ++nt8) {
                        const int nt = nt8 >> 1, hf = (nt8 & 1) * 2;
                        MMA16816(acc[mt][nt8],
                                 Ah[mt][0], Ah[mt][1], Ah[mt][2], Ah[mt][3],
                                 Bh[nt][hf], Bh[nt][hf + 1]);
                    }
#pragma unroll
                for (int mt = 0; mt < 2; ++mt)
#pragma unroll
                    for (int nt8 = 0; nt8 < 4; ++nt8) {
                        const int nt = nt8 >> 1, hf = (nt8 & 1) * 2;
                        MMA16816(acc[mt][nt8],
                                 Al[mt][0], Al[mt][1], Al[mt][2], Al[mt][3],
                                 Bh[nt][hf], Bh[nt][hf + 1]);
                    }
#pragma unroll
                for (int mt = 0; mt < 2; ++mt)
#pragma unroll
                    for (int nt8 = 0; nt8 < 4; ++nt8) {
                        const int nt = nt8 >> 1, hf = (nt8 & 1) * 2;
                        MMA16816(acc[mt][nt8],
                                 Ah[mt][0], Ah[mt][1], Ah[mt][2], Ah[mt][3],
                                 Bl[nt][hf], Bl[nt][hf + 1]);
                    }
            }
        }

        // ---- epilogue: bias+relu+W3 from register fragments ----
        const int g  = lane >> 2;
        const int c0 = (lane & 3) * 2;
        float p[4];
#pragma unroll
        for (int mt = 0; mt < 2; ++mt) {
            float s0 = 0.f, s1 = 0.f;
#pragma unroll
            for (int nt8 = 0; nt8 < 4; ++nt8) {
                const int n = n0 + nt8 * 8 + c0;
                const float w0 = sw3[n], w1 = sw3[n + 1];
                const float bb0 = sb1[n], bb1 = sb1[n + 1];
                s0 = fmaf(fmaxf(acc[mt][nt8][0] + bb0, 0.f), w0, s0);
                s0 = fmaf(fmaxf(acc[mt][nt8][1] + bb1, 0.f), w1, s0);
                s1 = fmaf(fmaxf(acc[mt][nt8][2] + bb0, 0.f), w0, s1);
                s1 = fmaf(fmaxf(acc[mt][nt8][3] + bb1, 0.f), w1, s1);
            }
            p[mt * 2 + 0] = s0;
            p[mt * 2 + 1] = s1;
        }
#pragma unroll
        for (int i = 0; i < 4; ++i) {
            p[i] += __shfl_xor_sync(0xffffffffu, p[i], 1);
            p[i] += __shfl_xor_sync(0xffffffffu, p[i], 2);
        }
        if ((lane & 3) == 0) {
#pragma unroll
            for (int i = 0; i < 4; ++i) {
                const int m = m0 + (i >> 1) * 16 + (i & 1) * 8 + g;
                spart[m * 4 + warp_n] = p[i];
            }
        }
        isrc = nsrc;          // roll prefetched indices into place
        idst = ndst;
        __syncthreads();
        if (tid < TILE_M) {
            const int ge = e0 + tid;
            if (ge < E) {
                float tot = spart[tid * 4 + 0] + spart[tid * 4 + 1]
                          + spart[tid * 4 + 2] + spart[tid * 4 + 3] + bb3;
                out[ge] = 1.0f / (1.0f + __expf(-tot));
            }
        }
        __syncthreads();
    }
}

extern "C" void kernel_launch(void* const* d_in, const int* in_sizes, int n_in,
                              void* d_out, int out_size) {
    const float* zi = (const float*)d_in[0];
    const float* zj = (const float*)d_in[1];
    const int*   src = (const int*)d_in[2];
    const int*   dst = (const int*)d_in[3];
    const float* W1 = (const float*)d_in[4];
    const float* b1 = (const float*)d_in[5];
    const float* W3 = (const float*)d_in[6];
    const float* b3 = (const float*)d_in[7];
    float* out = (float*)d_out;

    const int E = in_sizes[2];
    const int ntiles = (E + TILE_M - 1) / TILE_M;

    cudaFuncSetAttribute(edge_mlp_hmma,
                         cudaFuncAttributeMaxDynamicSharedMemorySize, SMEM_REQ);
    edge_mlp_hmma<<<GRID, THREADS, SMEM_REQ>>>(zi, zj, src, dst, W1, b1, W3, b3,
                                               out, E, ntiles);
}